// round 17
// baseline (speedup 1.0000x reference)
#include <cuda_runtime.h>
#include <cstdint>

#define BIGV 1e10f
#define TT 1024
#define BB 32
#define DD 64
#define NDIAG 2047   // row+col in [0, 2046]

// Diagonal-major cost scratch: g_cost[b][d][row], d = row+col.
static __device__ float g_cost[(size_t)BB * NDIAG * TT];
// Inter-CTA sentinel halo: qNaN = not ready; each slot written exactly once.
static __device__ float g_halo[BB][2048];

// ---------------------------------------------------------------------------
// Kernel A: cost matrix — EXACT round-1 version (known 174us).
// ---------------------------------------------------------------------------
__global__ __launch_bounds__(256) void cost_kernel(const float* __restrict__ x,
                                                   const float* __restrict__ y) {
    const int bz = blockIdx.z;
    const int br = blockIdx.y;
    const int bc = blockIdx.x;
    const int tid = threadIdx.x;

    __shared__ float arena[2 * 64 * 65];
    __shared__ float x2s[64], y2s[64];
    float* xsT = arena;
    float* ysT = arena + 64 * 65;
    float (*res)[72] = (float (*)[72])arena;

    const float* xb = x + ((size_t)bz * TT + br * 64) * DD;
    const float* yb = y + ((size_t)bz * TT + bc * 64) * DD;

    #pragma unroll
    for (int i = 0; i < 16; i++) {
        int idx = tid + i * 256;
        int r = idx >> 6;
        int d = idx & 63;
        xsT[d * 65 + r] = xb[r * DD + d];
        ysT[d * 65 + r] = yb[r * DD + d];
    }
    __syncthreads();

    if (tid < 64) {
        float s = 0.f;
        #pragma unroll
        for (int k = 0; k < 64; k++) { float v = xsT[k * 65 + tid]; s = fmaf(v, v, s); }
        x2s[tid] = s;
    } else if (tid < 128) {
        int c = tid - 64;
        float s = 0.f;
        #pragma unroll
        for (int k = 0; k < 64; k++) { float v = ysT[k * 65 + c]; s = fmaf(v, v, s); }
        y2s[c] = s;
    }

    const int tx = tid & 15;
    const int ty = tid >> 4;
    float acc[4][4] = {};
    #pragma unroll
    for (int k = 0; k < 64; k++) {
        float xr[4], yc[4];
        #pragma unroll
        for (int r = 0; r < 4; r++) xr[r] = xsT[k * 65 + ty * 4 + r];
        #pragma unroll
        for (int c = 0; c < 4; c++) yc[c] = ysT[k * 65 + tx * 4 + c];
        #pragma unroll
        for (int r = 0; r < 4; r++)
            #pragma unroll
            for (int c = 0; c < 4; c++)
                acc[r][c] = fmaf(xr[r], yc[c], acc[r][c]);
    }
    __syncthreads();

    float xr2[4], yc2[4];
    #pragma unroll
    for (int r = 0; r < 4; r++) xr2[r] = x2s[ty * 4 + r];
    #pragma unroll
    for (int c = 0; c < 4; c++) yc2[c] = y2s[tx * 4 + c];
    #pragma unroll
    for (int r = 0; r < 4; r++)
        #pragma unroll
        for (int c = 0; c < 4; c++)
            res[ty * 4 + r][tx * 4 + c] =
                fmaxf(xr2[r] + yc2[c] - 2.0f * acc[r][c], 0.0f);
    __syncthreads();

    const int wid = tid >> 5, lane = tid & 31;
    const int dbase = br * 64 + bc * 64;
    for (int dl = wid; dl < 127; dl += 8) {
        int rlo = dl > 63 ? dl - 63 : 0;
        int rhi = dl < 63 ? dl : 63;
        size_t gbase = ((size_t)bz * NDIAG + (dbase + dl)) * TT + (size_t)br * 64;
        for (int r0 = rlo; r0 <= rhi; r0 += 32) {
            int r = r0 + lane;
            if (r <= rhi) g_cost[gbase + r] = res[r][dl - r];
        }
    }
}

// NaN-fill the sentinel halo before each dp launch (graph-replay safe).
__global__ void init_kernel() {
    const float SENT = __int_as_float(0x7fc00000);
    int i = blockIdx.x * blockDim.x + threadIdx.x;   // 0..65535
    ((float*)g_halo)[i] = SENT;
}

__device__ __forceinline__ float softmin3(float a, float bb, float c) {
    float mnab = fminf(a, bb);
    float mxab = fmaxf(a, bb);
    float mn   = fminf(mnab, c);
    float hi   = fmaxf(mxab, c);
    float mid  = fmaxf(mnab, fminf(mxab, c));
    float sum  = 1.0f + __expf(mn - mid) + __expf(mn - hi);
    return mn - __logf(sum);
}

// ---------------------------------------------------------------------------
// Kernel B: R13 DP split across 2 plain CTAs per batch (64 CTAs x 256 thr,
// 8 warps = 2/SMSP) -> 2x the MUFU/issue pipes per batch. The single new
// mechanism vs R13: the CTA boundary halo goes through a gmem SENTINEL
// array. DP values are never NaN and each slot is written exactly once, so
// a non-NaN word IS its ready flag: producer lane31 fires 8 __stcg per
// segment (no fence, no counter, never blocks); the consumer warp polls
// with __ldcg (L1-bypassed; value sits in L2 ~1 segment before needed).
// All intra-CTA machinery byte-identical to R13.
// ---------------------------------------------------------------------------
#define SEG 8
#define NSEG 256   // SEG*NSEG = 2048 >= 2047 diagonals (k = 2..2049)
#define HALO_BYTES (7 * 2048 * 4)

__global__ __launch_bounds__(256) void dp_kernel(float* __restrict__ out) {
    extern __shared__ float halo_sm[];   // [7][2048]
    __shared__ int prog[8];

    const int cta = blockIdx.x;       // 0..63
    const int b = cta >> 1;           // batch
    const int q = cta & 1;            // half (0: rows 0..511, 1: rows 512..1023)
    const int t = threadIdx.x;        // 0..255
    const int lane = t & 31;
    const int w = t >> 5;             // warp 0..7
    const int W = q * 8 + w;          // global 64-row band 0..15
    const int r0 = W * 64 + (lane << 1);  // owned rows r0, r0+1

    if (t < 8) prog[t] = 0;
    __syncthreads();
    volatile int* vprog = prog;

    float v1_0 = BIGV, v1_1 = BIGV;   // d_{k-1}[r0+1], d_{k-1}[r0+2]
    float v2_0 = BIGV, v2_1 = BIGV;   // d_{k-2}[...]
    float L1 = BIGV;                  // d_{k-1}[r0]
    float L2 = (W == 0 && lane == 0) ? 0.0f : BIGV;   // d0[0] = 0

    const float* costbase = g_cost + (size_t)b * NDIAG * TT + r0;
    const int kminA = r0 + 2;
    const int kmaxA = r0 + 2 + TT;

    // band-level windows (uniform across warp)
    const int W0 = 64 * W + 2;
    const int W1 = 64 * W + 64 + TT;
    const int F0 = 64 * W + 65;
    const int F1 = 64 * W + 1 + TT;
    const int P0 = 64 * W + 64;
    const int P1 = 64 * W + 2 + TT;

    float* myhalo = &halo_sm[w * 2048];            // valid only for w<7
    const float* lhalo = &halo_sm[(w - 1) * 2048]; // valid only for w>0

    const bool gm_produce = (q == 0) && (w == 7);
    const bool gm_consume = (q == 1) && (w == 0);
    float* ghalo = g_halo[b];

    float res = BIGV;
    float2 cbuf[SEG], nbuf[SEG];
    float hb[SEG];
    #pragma unroll
    for (int j = 0; j < SEG; j++) hb[j] = BIGV;    // W==0 keeps BIGV (d_k[0]=BIG)

    // preload segment 0 costs (masked)
    #pragma unroll
    for (int j = 0; j < SEG; j++) {
        int k = 2 + j;
        cbuf[j] = make_float2(0.f, 0.f);
        if ((k >= kminA) & (k <= kmaxA))
            cbuf[j] = *(const float2*)(costbase + (size_t)(k - 2) * TT);
    }

    int k0 = 2;
    for (int s = 0; s < NSEG; s++) {
        const bool active = (k0 <= W1) & (k0 + SEG - 1 >= W0);

        // ---- gate + batched halo read (once per segment) ----
        if (active && (W > 0)) {
            if (w > 0) {
                if (vprog[w - 1] < s + 1) {
                    while (vprog[w - 1] < s + 1) __nanosleep(20);
                }
                __threadfence_block();
                float4 h0 = *(const float4*)&lhalo[k0 - 2];
                float4 h1 = *(const float4*)&lhalo[k0 + 2];
                hb[0] = h0.x; hb[1] = h0.y; hb[2] = h0.z; hb[3] = h0.w;
                hb[4] = h1.x; hb[5] = h1.y; hb[6] = h1.z; hb[7] = h1.w;
            } else {   // gm_consume: poll sentinel words in L2
                float4 h0 = __ldcg((const float4*)&ghalo[k0 - 2]);
                float4 h1 = __ldcg((const float4*)&ghalo[k0 + 2]);
                while ((h0.x != h0.x) | (h0.y != h0.y) | (h0.z != h0.z) |
                       (h0.w != h0.w) | (h1.x != h1.x) | (h1.y != h1.y) |
                       (h1.z != h1.z) | (h1.w != h1.w)) {
                    __nanosleep(32);
                    h0 = __ldcg((const float4*)&ghalo[k0 - 2]);
                    h1 = __ldcg((const float4*)&ghalo[k0 + 2]);
                }
                hb[0] = h0.x; hb[1] = h0.y; hb[2] = h0.z; hb[3] = h0.w;
                hb[4] = h1.x; hb[5] = h1.y; hb[6] = h1.z; hb[7] = h1.w;
            }
        }

        // ---- prefetch next segment costs ----
        const int k0n = k0 + SEG;
        if ((k0n <= W1) & (k0n + SEG - 1 >= W0) & (s + 1 < NSEG)) {
            const float* p = costbase + (size_t)(k0n - 2) * TT;
            if ((k0n >= P0) & (k0n + SEG - 1 <= P1)) {
                #pragma unroll
                for (int j = 0; j < SEG; j++)
                    nbuf[j] = *(const float2*)(p + (size_t)j * TT);
            } else {
                #pragma unroll
                for (int j = 0; j < SEG; j++) {
                    int k = k0n + j;
                    nbuf[j] = make_float2(0.f, 0.f);
                    if ((k >= kminA) & (k <= kmaxA))
                        nbuf[j] = *(const float2*)(p + (size_t)j * TT);
                }
            }
        }

        // ---- compute segment (branch-free, memory-free inner loops) ----
        float sh[SEG];
        if (!active) {
            #pragma unroll
            for (int j = 0; j < SEG; j++) sh[j] = BIGV;
        } else if ((k0 >= F0) & (k0 + SEG - 1 <= F1)) {
            // interior fast path
            #pragma unroll
            for (int j = 0; j < SEG; j++) {
                float cur1 = cbuf[j].y + softmin3(v2_0, v1_0, v1_1);
                float cur0 = cbuf[j].x + softmin3(L2, L1, v1_0);
                float nb = __shfl_up_sync(0xffffffffu, cur1, 1);
                nb = (lane == 0) ? hb[j] : nb;     // SEL, no branch
                sh[j] = cur1;
                L2 = L1; L1 = nb;
                v2_0 = v1_0; v2_1 = v1_1;
                v1_0 = cur0; v1_1 = cur1;
                res = cur1;
            }
        } else {
            // edge path (masked with selects; branch-free per diag)
            #pragma unroll
            for (int j = 0; j < SEG; j++) {
                const int k = k0 + j;
                const int rlo = k - 1 - TT;
                const int rhi = k - 2;
                const bool tv = (k >= kminA) & (k <= kmaxA);

                float sm1 = softmin3(v2_0, v1_0, v1_1);
                float sm0 = softmin3(L2, L1, v1_0);
                int r1 = r0 + 1;
                float cur1 = (tv & (r1 >= rlo) & (r1 <= rhi)) ? cbuf[j].y + sm1 : BIGV;
                float cur0 = (tv & (r0 >= rlo) & (r0 <= rhi)) ? cbuf[j].x + sm0 : BIGV;
                res = tv ? cur1 : res;

                float nb = __shfl_up_sync(0xffffffffu, cur1, 1);
                nb = (lane == 0) ? hb[j] : nb;
                sh[j] = cur1;
                L2 = L1; L1 = nb;
                v2_0 = v1_0; v2_1 = v1_1;
                v1_0 = cur0; v1_1 = cur1;
            }
        }

        // ---- epilogue: batched halo publish ----
        if (w < 7) {
            if (lane == 31) {
                *(float4*)&myhalo[k0 - 2] = make_float4(sh[0], sh[1], sh[2], sh[3]);
                *(float4*)&myhalo[k0 + 2] = make_float4(sh[4], sh[5], sh[6], sh[7]);
            }
            __threadfence_block();
            if (lane == 0) vprog[w] = s + 1;
        } else if (gm_produce) {
            if (lane == 31) {
                #pragma unroll
                for (int j = 0; j < SEG; j++)
                    __stcg(&ghalo[k0 - 2 + j], sh[j]);   // fire-and-forget
            }
        }

        #pragma unroll
        for (int j = 0; j < SEG; j++) cbuf[j] = nbuf[j];
        k0 = k0n;
    }

    // answer = d_{2T}[T]: row 1023 -> q=1, warp 7, lane 31, second row (k=2048)
    if (q == 1 && t == 255) out[b] = res;
}

extern "C" void kernel_launch(void* const* d_in, const int* in_sizes, int n_in,
                              void* d_out, int out_size) {
    const float* x = (const float*)d_in[0];
    const float* y = (const float*)d_in[1];
    float* out = (float*)d_out;

    cudaFuncSetAttribute(dp_kernel,
                         cudaFuncAttributeMaxDynamicSharedMemorySize, HALO_BYTES);

    dim3 gridA(TT / 64, TT / 64, BB);   // (16, 16, 32)
    cost_kernel<<<gridA, 256>>>(x, y);
    init_kernel<<<256, 256>>>();        // NaN-fill g_halo (65536 words)
    dp_kernel<<<BB * 2, 256, HALO_BYTES>>>(out);
}